// round 13
// baseline (speedup 1.0000x reference)
#include <cuda_runtime.h>
#include <cstdint>

// Fixed problem geometry: H=W=2048, step=2 -> nu=nv=1024, N=2^20 nodes.
constexpr int NU = 1024;
constexpr int NV = 1024;
constexpr int N  = NU * NV;
constexpr int W  = 2048;
constexpr int ROWF = 6 * W;        // floats per pixel row (12288)

// Output layout (floats): pts[3N] nrm[3N] radii[N] lens[4N] areas[2N]
constexpr int OFF_PTS  = 0;
constexpr int OFF_NRM  = 3 * N;
constexpr int OFF_RAD  = 6 * N;
constexpr int OFF_LEN  = 7 * N;
constexpr int OFF_AREA = 11 * N;

constexpr int TPB = 256;

__device__ __forceinline__ float fast_sqrt(float x) {
    return x * rsqrtf(fmaxf(x, 1e-30f));   // x==0 -> 0, not NaN
}

struct F3 { float x, y, z; };

__device__ __forceinline__ float dist3(const F3& a, const F3& b) {
    float dx = a.x - b.x, dy = a.y - b.y, dz = a.z - b.z;
    return fast_sqrt(dx * dx + dy * dy + dz * dz);
}

__device__ __forceinline__ F3 sub3(const F3& a, const F3& b) {
    F3 r; r.x = a.x - b.x; r.y = a.y - b.y; r.z = a.z - b.z; return r;
}

__device__ __forceinline__ float cross_area(const F3& u, const F3& v) {
    float cx = u.y * v.z - u.z * v.y;
    float cy = u.z * v.x - u.x * v.z;
    float cz = u.x * v.y - u.y * v.x;
    return 0.5f * fast_sqrt(cx * cx + cy * cy + cz * cz + 1e-13f);
}

__device__ __forceinline__ void st2(float* __restrict__ p, int off, float a, float b) {
    *reinterpret_cast<float2*>(p + off) = make_float2(a, b);
}

__device__ __forceinline__ F3 loadA(const float* __restrict__ p, int jv, int iu) {
    int off = jv * ROWF + iu * 6;
    float2 ab = *reinterpret_cast<const float2*>(p + off);
    F3 r; r.x = ab.x; r.y = ab.y; r.z = p[off + 2];
    return r;
}

// load anchor pair (cols iu, iu+1) of grid row jv; iu even -> 48B aligned
__device__ __forceinline__ void loadPair(const float* __restrict__ p, int jv, int iu,
                                         F3& A, F3& B) {
    const float* b = p + jv * ROWF + 6 * iu;
    float4 q0 = *reinterpret_cast<const float4*>(b);
    float4 q1 = *reinterpret_cast<const float4*>(b + 4);
    float  q2 = b[8];
    A.x = q0.x; A.y = q0.y; A.z = q0.z;
    B.x = q1.z; B.y = q1.w; B.z = q2;
}

__device__ __forceinline__ F3 shup3(const F3& v) {
    F3 r;
    r.x = __shfl_up_sync(0xffffffffu, v.x, 1);
    r.y = __shfl_up_sync(0xffffffffu, v.y, 1);
    r.z = __shfl_up_sync(0xffffffffu, v.z, 1);
    return r;
}
__device__ __forceinline__ F3 shdn3(const F3& v) {
    F3 r;
    r.x = __shfl_down_sync(0xffffffffu, v.x, 1);
    r.y = __shfl_down_sync(0xffffffffu, v.y, 1);
    r.z = __shfl_down_sync(0xffffffffu, v.z, 1);
    return r;
}

// ---------------------------------------------------------------------------
// 2x2 quad per thread: nodes a=(iu,jv) b=(iu+1,jv) c=(iu,jv+1) d=(iu+1,jv+1),
// iu,jv even. Bottom row's up-incident edges come from top row's registers;
// horizontal sharing via warp shuffles. Top row de is always true (jv<=1022);
// re(a), re(c), le(b), le(d), ue(c), ue(d) always true.
// ---------------------------------------------------------------------------
__global__ __launch_bounds__(TPB, 4)
void k_quad(const float* __restrict__ cand,
            const float* __restrict__ cnrm,
            float* __restrict__ out) {
    const int p    = blockIdx.x * TPB + threadIdx.x;
    const int lane = threadIdx.x & 31;
    const int px   = p & 511;             // pair-column index
    const int iu   = px << 1;             // even
    const int jv   = (p >> 9) << 1;       // even
    const int k    = jv * NU + iu;

    const bool le   = iu > 0;
    const bool re_b = iu < NU - 2;
    const bool ue   = jv > 0;
    const bool de_c = jv < NV - 2;        // bottom row has down
    const int jU = ue ? jv - 1 : 0;
    const int jC = jv;
    const int jD = jv + 1;
    const int jE = de_c ? jv + 2 : NV - 1;

    // --- point loads: 4 rows x own pair ---
    F3 Ca, Cb, Da, Db, Ea, Eb, Ua, Ub;
    loadPair(cand, jC, iu, Ca, Cb);
    loadPair(cand, jD, iu, Da, Db);
    loadPair(cand, jE, iu, Ea, Eb);
    loadPair(cand, jU, iu, Ua, Ub);

    // pts out immediately
    {
        const int p3 = OFF_PTS + 3 * k;
        st2(out, p3 + 0, Ca.x, Ca.y); st2(out, p3 + 2, Ca.z, Cb.x); st2(out, p3 + 4, Cb.y, Cb.z);
        const int q3 = OFF_PTS + 3 * (k + NU);
        st2(out, q3 + 0, Da.x, Da.y); st2(out, q3 + 2, Da.z, Db.x); st2(out, q3 + 4, Db.y, Db.z);
    }
    // nrm: load + store, never live
    {
        F3 Nt1, Nt2;
        loadPair(cnrm, jC, iu, Nt1, Nt2);
        const int n3 = OFF_NRM + 3 * k;
        st2(out, n3 + 0, Nt1.x, Nt1.y); st2(out, n3 + 2, Nt1.z, Nt2.x); st2(out, n3 + 4, Nt2.y, Nt2.z);
        loadPair(cnrm, jD, iu, Nt1, Nt2);
        const int m3 = OFF_NRM + 3 * (k + NU);
        st2(out, m3 + 0, Nt1.x, Nt1.y); st2(out, m3 + 2, Nt1.z, Nt2.x); st2(out, m3 + 4, Nt2.y, Nt2.z);
    }

    // --- neighbor points via shuffles, halo patches via LDG ---
    F3 Ul = shup3(Ub);
    F3 Ur = shdn3(Ua);
    F3 Cr = shdn3(Ca);
    F3 Dr = shdn3(Da);
    F3 Er = shdn3(Ea);
    if (lane == 0) {
        // FIX (R12 bug): lane 0's shfl_up is a self-copy; Ul must be loaded.
        int iuL = max(iu - 1, 0);         // clamp; (le&&ue)-guarded use
        Ul = loadA(cand, jU, iuL);
    }
    if (lane == 31) {
        int iR = min(iu + 2, NU - 1);     // clamp; re_b-guarded use
        Ur = loadA(cand, jU, iR);
        Cr = loadA(cand, jC, iR);
        Dr = loadA(cand, jD, iR);
        Er = loadA(cand, jE, iR);
    }

    // --- own distances (top row jv, bottom row jv+1) ---
    float dRa = dist3(Ca, Cb), dGa = dist3(Ca, Db), dDa = dist3(Ca, Da), dAa = dist3(Cb, Da);
    float dRb = dist3(Cb, Cr), dGb = dist3(Cb, Dr), dDb = dist3(Cb, Db), dAb = dist3(Cr, Db);
    float dRc = dist3(Da, Db), dGc = dist3(Da, Eb), dDc = dist3(Da, Ea), dAc = dist3(Db, Ea);
    float dRd = dist3(Db, Dr), dGd = dist3(Db, Er), dDd = dist3(Db, Eb), dAd = dist3(Dr, Eb);

    // --- up-row distances (flag-guarded by ue) ---
    float dUDa = dist3(Ua, Ca);   // D[k-NU]
    float dUAa = dist3(Ub, Ca);   // A[k-NU]
    float dULa = dist3(Ul, Ca);   // G[k-NU-1]
    float dUGb = dist3(Ua, Cb);   // G[k-NU]
    float dUDb = dist3(Ub, Cb);   // D[k+1-NU]
    float dUAb = dist3(Ur, Cb);   // A[k+1-NU]

    // --- left-neighbor distances via shuffle; lane 0 recomputes ---
    float sRl_t = __shfl_up_sync(0xffffffffu, dRb, 1);   // R[k-1]
    float sAl_t = __shfl_up_sync(0xffffffffu, dAb, 1);   // A[k-1]
    float sGl_t = __shfl_up_sync(0xffffffffu, dGb, 1);   // G[k-1]
    float sRl_b = __shfl_up_sync(0xffffffffu, dRd, 1);   // R[c-1]
    float sAl_b = __shfl_up_sync(0xffffffffu, dAd, 1);   // A[c-1]
    if (lane == 0) {
        int iuL = max(iu - 1, 0);         // clamp; le-guarded use
        F3 Cl = loadA(cand, jC, iuL);
        F3 Dl = loadA(cand, jD, iuL);
        F3 El = loadA(cand, jE, iuL);
        sRl_t = dist3(Cl, Ca);
        sAl_t = dist3(Ca, Dl);
        sGl_t = dist3(Cl, Da);
        sRl_b = dist3(Dl, Da);
        sAl_b = dist3(Da, El);
    }

    // --- areas ---
    float a0a = cross_area(sub3(Cb, Ca), sub3(Db, Ca));
    float a1a = cross_area(sub3(Db, Ca), sub3(Da, Ca));
    float a0b = cross_area(sub3(Cr, Cb), sub3(Dr, Cb));
    float a1b = cross_area(sub3(Dr, Cb), sub3(Db, Cb));
    float a0c = cross_area(sub3(Db, Da), sub3(Eb, Da));
    float a1c = cross_area(sub3(Eb, Da), sub3(Ea, Da));
    float a0d = cross_area(sub3(Dr, Db), sub3(Er, Db));
    float a1d = cross_area(sub3(Er, Db), sub3(Eb, Db));

    // --- radii ---
    float suma = dRa + dGa + dDa; float cnta = 3.0f;
    if (ue) { suma += dUDa + dUAa; cnta += 2.0f; }
    if (le) {
        suma += sRl_t + sAl_t; cnta += 2.0f;
        if (ue) { suma += dULa; cnta += 1.0f; }
    }
    float sumb = dRa + dAa + dDb; float cntb = 3.0f;
    if (re_b) { sumb += dRb + dGb; cntb += 2.0f; }
    if (ue) {
        sumb += dUGb + dUDb; cntb += 2.0f;
        if (re_b) { sumb += dUAb; cntb += 1.0f; }
    }
    float sumc = dRc + dDa + dAa; float cntc = 3.0f;
    if (de_c) { sumc += dGc + dDc; cntc += 2.0f; }
    if (le) {
        sumc += sRl_b + sGl_t; cntc += 2.0f;
        if (de_c) { sumc += sAl_b; cntc += 1.0f; }
    }
    float sumd = dRc + dGa + dDb; float cntd = 3.0f;
    if (de_c) { sumd += dAc + dDd; cntd += 2.0f; }
    if (re_b) {
        sumd += dRd + dAb; cntd += 2.0f;
        if (de_c) { sumd += dGd; cntd += 1.0f; }
    }
    st2(out, OFF_RAD + k,      __fdividef(suma, cnta), __fdividef(sumb, cntb));
    st2(out, OFF_RAD + k + NU, __fdividef(sumc, cntc), __fdividef(sumd, cntd));

    // --- lens + areas stores (float2) ---
    const bool rdb = re_b && de_c;
    const int k2 = k + NU;
    st2(out, OFF_LEN + 0 * N + k, dRa, re_b ? dRb : 0.0f);
    st2(out, OFF_LEN + 1 * N + k, dGa, re_b ? dGb : 0.0f);
    st2(out, OFF_LEN + 2 * N + k, dDa, dDb);
    st2(out, OFF_LEN + 3 * N + k, dAa, re_b ? dAb : 0.0f);
    st2(out, OFF_AREA + 0 * N + k, a0a, re_b ? a0b : 0.0f);
    st2(out, OFF_AREA + 1 * N + k, a1a, re_b ? a1b : 0.0f);
    st2(out, OFF_LEN + 0 * N + k2, dRc,                 re_b ? dRd : 0.0f);
    st2(out, OFF_LEN + 1 * N + k2, de_c ? dGc : 0.0f,   rdb ? dGd : 0.0f);
    st2(out, OFF_LEN + 2 * N + k2, de_c ? dDc : 0.0f,   de_c ? dDd : 0.0f);
    st2(out, OFF_LEN + 3 * N + k2, de_c ? dAc : 0.0f,   rdb ? dAd : 0.0f);
    st2(out, OFF_AREA + 0 * N + k2, de_c ? a0c : 0.0f,  rdb ? a0d : 0.0f);
    st2(out, OFF_AREA + 1 * N + k2, de_c ? a1c : 0.0f,  rdb ? a1d : 0.0f);
}

// ---------------------------------------------------------------------------
// Launch
// ---------------------------------------------------------------------------
extern "C" void kernel_launch(void* const* d_in, const int* in_sizes, int n_in,
                              void* d_out, int out_size) {
    (void)in_sizes; (void)n_in; (void)out_size;
    const float* cand = (const float*)d_in[1];
    const float* cnrm = (const float*)d_in[2];
    float* out = (float*)d_out;

    k_quad<<<(N / 4) / TPB, TPB>>>(cand, cnrm, out);
}

// round 14
// speedup vs baseline: 1.0977x; 1.0977x over previous
#include <cuda_runtime.h>
#include <cstdint>

// Fixed problem geometry: H=W=2048, step=2 -> nu=nv=1024, N=2^20 nodes.
constexpr int NU = 1024;
constexpr int NV = 1024;
constexpr int N  = NU * NV;
constexpr int W  = 2048;
constexpr int ROWF = 6 * W;        // floats per pixel row (12288)

// Output layout (floats): pts[3N] nrm[3N] radii[N] lens[4N] areas[2N]
constexpr int OFF_PTS  = 0;
constexpr int OFF_NRM  = 3 * N;
constexpr int OFF_RAD  = 6 * N;
constexpr int OFF_LEN  = 7 * N;
constexpr int OFF_AREA = 11 * N;

constexpr int TPB = 256;

__device__ __forceinline__ float fast_sqrt(float x) {
    return x * rsqrtf(fmaxf(x, 1e-30f));   // x==0 -> 0, not NaN
}

struct F3 { float x, y, z; };

__device__ __forceinline__ float dist3(const F3& a, const F3& b) {
    float dx = a.x - b.x, dy = a.y - b.y, dz = a.z - b.z;
    return fast_sqrt(dx * dx + dy * dy + dz * dz);
}

__device__ __forceinline__ F3 sub3(const F3& a, const F3& b) {
    F3 r; r.x = a.x - b.x; r.y = a.y - b.y; r.z = a.z - b.z; return r;
}

__device__ __forceinline__ float cross_area(const F3& u, const F3& v) {
    float cx = u.y * v.z - u.z * v.y;
    float cy = u.z * v.x - u.x * v.z;
    float cz = u.x * v.y - u.y * v.x;
    return 0.5f * fast_sqrt(cx * cx + cy * cy + cz * cz + 1e-13f);
}

__device__ __forceinline__ F3 loadA(const float* __restrict__ p, int jv, int iu) {
    int off = jv * ROWF + iu * 6;              // anchor pixel, 8B aligned
    float2 ab = *reinterpret_cast<const float2*>(p + off);
    F3 r; r.x = ab.x; r.y = ab.y; r.z = p[off + 2];
    return r;
}

__device__ __forceinline__ F3 shup3(const F3& v) {
    F3 r;
    r.x = __shfl_up_sync(0xffffffffu, v.x, 1);
    r.y = __shfl_up_sync(0xffffffffu, v.y, 1);
    r.z = __shfl_up_sync(0xffffffffu, v.z, 1);
    return r;
}
__device__ __forceinline__ F3 shdn3(const F3& v) {
    F3 r;
    r.x = __shfl_down_sync(0xffffffffu, v.x, 1);
    r.y = __shfl_down_sync(0xffffffffu, v.y, 1);
    r.z = __shfl_down_sync(0xffffffffu, v.z, 1);
    return r;
}

// ---------------------------------------------------------------------------
// One node per thread; warp = 32 consecutive iu within one grid row
// (1024 % 256 == 0 -> blocks/warps never straddle rows). Neighbor points via
// warp shuffles; lanes 0/31 patch halos with predicated LDG (L1 hits).
// ---------------------------------------------------------------------------
__global__ __launch_bounds__(TPB)
void k_warp(const float* __restrict__ cand,
            const float* __restrict__ cnrm,
            float* __restrict__ out) {
    const int k    = blockIdx.x * TPB + threadIdx.x;
    const int lane = threadIdx.x & 31;
    const int iu   = k & (NU - 1);
    const int jv   = k >> 10;

    const bool re = iu < NU - 1;
    const bool de = jv < NV - 1;
    const bool le = iu > 0;
    const bool ue = jv > 0;
    const bool rd = re && de;

    const int jU = ue ? jv - 1 : 0;    // clamped, flag-guarded
    const int jD = de ? jv + 1 : jv;

    // --- own-column point loads (3 rows) + normal ---
    F3 P0 = loadA(cand, jv, iu);
    F3 PD = loadA(cand, jD, iu);
    F3 PU = loadA(cand, jU, iu);
    F3 NR = loadA(cnrm, jv, iu);

    // pts / nrm out immediately (shortens live ranges)
    {
        const int p3 = OFF_PTS + 3 * k;
        out[p3 + 0] = P0.x; out[p3 + 1] = P0.y; out[p3 + 2] = P0.z;
        const int n3 = OFF_NRM + 3 * k;
        out[n3 + 0] = NR.x; out[n3 + 1] = NR.y; out[n3 + 2] = NR.z;
    }

    // --- neighbor points via shuffles; halo patch by LDG ---
    F3 PR  = shdn3(P0);   // (iu+1, jv)
    F3 PG  = shdn3(PD);   // (iu+1, jD)
    F3 PUR = shdn3(PU);   // (iu+1, jU)
    F3 PUL = shup3(PU);   // (iu-1, jU)
    if (lane == 31) {
        int iR = re ? iu + 1 : iu;     // clamp; re-guarded
        PR  = loadA(cand, jv, iR);
        PG  = loadA(cand, jD, iR);
        PUR = loadA(cand, jU, iR);
    }
    if (lane == 0) {
        int iL = le ? iu - 1 : 0;      // clamp; (le&&ue)-guarded
        PUL = loadA(cand, jU, iL);
    }

    // --- own distances ---
    float dR = dist3(P0, PR);
    float dG = dist3(P0, PG);
    float dD = dist3(P0, PD);
    float dA = dist3(PR, PD);

    // --- up-row incident distances (ue-guarded) ---
    float dDu  = dist3(PU,  P0);   // D[k-NU]
    float dAu  = dist3(PUR, P0);   // A[k-NU]
    float dGul = dist3(PUL, P0);   // G[k-NU-1]

    // --- left incident distances via shuffle; lane 0 recomputes ---
    float dRl = __shfl_up_sync(0xffffffffu, dR, 1);   // R[k-1]
    float dAl = __shfl_up_sync(0xffffffffu, dA, 1);   // A[k-1]
    if (lane == 0) {
        int iL = le ? iu - 1 : 0;     // clamp; le-guarded
        F3 Pl  = loadA(cand, jv, iL);
        F3 PDl = loadA(cand, jD, iL);
        dRl = dist3(Pl, P0);
        dAl = dist3(P0, PDl);          // A[k-1] = |p(k) - p(k-1+NU)|
    }

    // --- areas ---
    float a0 = cross_area(sub3(PR, P0), sub3(PG, P0));
    float a1 = cross_area(sub3(PG, P0), sub3(PD, P0));

    // --- radii ---
    float sum = 0.0f, cnt = 0.0f;
    if (re) { sum += dR;  cnt += 1.0f; }
    if (rd) { sum += dG;  cnt += 1.0f; }
    if (de) { sum += dD;  cnt += 1.0f; }
    if (le && de) { sum += dAl;  cnt += 1.0f; }
    if (le)       { sum += dRl;  cnt += 1.0f; }
    if (le && ue) { sum += dGul; cnt += 1.0f; }
    if (ue)       { sum += dDu;  cnt += 1.0f; }
    if (re && ue) { sum += dAu;  cnt += 1.0f; }
    out[OFF_RAD + k] = __fdividef(sum, fmaxf(cnt, 1.0f));

    // --- lens / areas ---
    out[OFF_LEN + 0 * N + k] = re ? dR : 0.0f;
    out[OFF_LEN + 1 * N + k] = rd ? dG : 0.0f;
    out[OFF_LEN + 2 * N + k] = de ? dD : 0.0f;
    out[OFF_LEN + 3 * N + k] = rd ? dA : 0.0f;
    out[OFF_AREA + 0 * N + k] = rd ? a0 : 0.0f;
    out[OFF_AREA + 1 * N + k] = rd ? a1 : 0.0f;
}

// ---------------------------------------------------------------------------
// Launch
// ---------------------------------------------------------------------------
extern "C" void kernel_launch(void* const* d_in, const int* in_sizes, int n_in,
                              void* d_out, int out_size) {
    (void)in_sizes; (void)n_in; (void)out_size;
    const float* cand = (const float*)d_in[1];
    const float* cnrm = (const float*)d_in[2];
    float* out = (float*)d_out;

    k_warp<<<N / TPB, TPB>>>(cand, cnrm, out);
}